// round 1
// baseline (speedup 1.0000x reference)
#include <cuda_runtime.h>
#include <math.h>

#define HIDDEN 2048
#define NHEADS 16
#define HEADD  128
#define BATCH  4
#define SEQ    2048
#define NTOK   (BATCH*SEQ)   /* 8192 */
#define QKVN   (3*HIDDEN)    /* 6144 */

// Scratch (device globals: the sanctioned no-alloc workaround)
__device__ float g_qkv[(size_t)NTOK * QKVN];    // ~201 MB
__device__ float g_attn[(size_t)NTOK * HIDDEN]; // ~67 MB

// ---------------------------------------------------------------------------
// SGEMM: C[M,N] = A[M,K] * B[N,K]^T + bias[N]
// Both A and B are K-contiguous row-major. Tiles 128x128x16, 8x8 per thread.
// Requires M%128==0, N%128==0, K%16==0 (true for all shapes here).
// ---------------------------------------------------------------------------
__global__ __launch_bounds__(256)
void sgemm_bt_bias(const float* __restrict__ A, const float* __restrict__ B,
                   const float* __restrict__ bias, float* __restrict__ C,
                   int M, int N, int K) {
    __shared__ float As[16][128];
    __shared__ float Bs[16][128];

    const int tid = threadIdx.x;
    const int ty  = tid >> 4;     // 0..15
    const int tx  = tid & 15;     // 0..15
    const int row0 = blockIdx.y * 128;
    const int col0 = blockIdx.x * 128;

    // loader: each thread moves 2 float4 of A and 2 of B per k-tile
    const int lr = tid >> 2;          // 0..63
    const int lc = (tid & 3) << 2;    // 0,4,8,12

    float acc[8][8];
    #pragma unroll
    for (int i = 0; i < 8; i++)
        #pragma unroll
        for (int j = 0; j < 8; j++) acc[i][j] = 0.f;

    for (int kt = 0; kt < K; kt += 16) {
        #pragma unroll
        for (int h = 0; h < 2; h++) {
            const int r = lr + h * 64;
            float4 va = *reinterpret_cast<const float4*>(&A[(size_t)(row0 + r) * K + kt + lc]);
            As[lc + 0][r] = va.x; As[lc + 1][r] = va.y;
            As[lc + 2][r] = va.z; As[lc + 3][r] = va.w;
            float4 vb = *reinterpret_cast<const float4*>(&B[(size_t)(col0 + r) * K + kt + lc]);
            Bs[lc + 0][r] = vb.x; Bs[lc + 1][r] = vb.y;
            Bs[lc + 2][r] = vb.z; Bs[lc + 3][r] = vb.w;
        }
        __syncthreads();

        #pragma unroll
        for (int k = 0; k < 16; k++) {
            float a[8], b[8];
            float4 a0 = *reinterpret_cast<const float4*>(&As[k][ty * 8]);
            float4 a1 = *reinterpret_cast<const float4*>(&As[k][ty * 8 + 4]);
            float4 b0 = *reinterpret_cast<const float4*>(&Bs[k][tx * 8]);
            float4 b1 = *reinterpret_cast<const float4*>(&Bs[k][tx * 8 + 4]);
            a[0]=a0.x;a[1]=a0.y;a[2]=a0.z;a[3]=a0.w;a[4]=a1.x;a[5]=a1.y;a[6]=a1.z;a[7]=a1.w;
            b[0]=b0.x;b[1]=b0.y;b[2]=b0.z;b[3]=b0.w;b[4]=b1.x;b[5]=b1.y;b[6]=b1.z;b[7]=b1.w;
            #pragma unroll
            for (int i = 0; i < 8; i++)
                #pragma unroll
                for (int j = 0; j < 8; j++)
                    acc[i][j] = fmaf(a[i], b[j], acc[i][j]);
        }
        __syncthreads();
    }

    #pragma unroll
    for (int i = 0; i < 8; i++) {
        const int row = row0 + ty * 8 + i;
        float* crow = &C[(size_t)row * N + col0 + tx * 8];
        #pragma unroll
        for (int j = 0; j < 8; j++)
            crow[j] = acc[i][j] + bias[col0 + tx * 8 + j];
    }
}

// ---------------------------------------------------------------------------
// Flash attention, fp32, causal. One block per (q-tile 64 rows, head, batch).
// 256 threads: ty=tid/16 owns q-rows 4ty..4ty+3, tx=tid%16 owns features.
// Smem: Qt[128][68] (d-major), Kt[128][68], V[64][132], P[64][68].
// ---------------------------------------------------------------------------
#define QT_STRIDE 68
#define V_STRIDE  132
#define SM_BYTES  ((128*QT_STRIDE + 128*QT_STRIDE + 64*V_STRIDE + 64*QT_STRIDE) * 4)

__global__ __launch_bounds__(256)
void flash_attn_kernel(const float* __restrict__ qkv, float* __restrict__ out) {
    extern __shared__ float sm[];
    float* sQt = sm;                         // [128][68]
    float* sKt = sQt + 128 * QT_STRIDE;      // [128][68]
    float* sV  = sKt + 128 * QT_STRIDE;      // [64][132]
    float* sP  = sV  + 64  * V_STRIDE;       // [64][68]

    const int tid = threadIdx.x;
    const int ty  = tid >> 4;   // 0..15
    const int tx  = tid & 15;   // 0..15
    const int qt  = blockIdx.x;
    const int h   = blockIdx.y;
    const int b   = blockIdx.z;

    const float scale = 0.08838834764831845f; // 1/sqrt(128)

    // Load Q tile (scaled) transposed into sQt[d][r]
    const float* qbase = qkv + ((size_t)(b * SEQ + qt * 64)) * QKVN + h * HEADD;
    for (int idx = tid; idx < 64 * 128; idx += 256) {
        const int r = idx >> 7, d = idx & 127;
        sQt[d * QT_STRIDE + r] = qbase[(size_t)r * QKVN + d] * scale;
    }

    float O[4][8];
    float m_i[4], l_i[4];
    #pragma unroll
    for (int i = 0; i < 4; i++) {
        m_i[i] = -INFINITY; l_i[i] = 0.f;
        #pragma unroll
        for (int j = 0; j < 8; j++) O[i][j] = 0.f;
    }

    for (int kt = 0; kt <= qt; kt++) {
        const float* kbase = qkv + ((size_t)(b * SEQ + kt * 64)) * QKVN + HIDDEN + h * HEADD;
        const float* vbase = kbase + HIDDEN;
        for (int idx = tid; idx < 64 * 128; idx += 256) {
            const int r = idx >> 7, d = idx & 127;
            sKt[d * QT_STRIDE + r] = kbase[(size_t)r * QKVN + d];
            sV[r * V_STRIDE + d]   = vbase[(size_t)r * QKVN + d];
        }
        __syncthreads();  // K/V (and on first iter, Q) visible

        // S[4][4] = Q rows (4ty+i) x K cols (4tx+j)
        float s[4][4];
        #pragma unroll
        for (int i = 0; i < 4; i++)
            #pragma unroll
            for (int j = 0; j < 4; j++) s[i][j] = 0.f;

        #pragma unroll 2
        for (int d = 0; d < 128; d++) {
            float4 a4 = *reinterpret_cast<const float4*>(&sQt[d * QT_STRIDE + 4 * ty]);
            float4 b4 = *reinterpret_cast<const float4*>(&sKt[d * QT_STRIDE + 4 * tx]);
            const float a[4] = {a4.x, a4.y, a4.z, a4.w};
            const float bb[4] = {b4.x, b4.y, b4.z, b4.w};
            #pragma unroll
            for (int i = 0; i < 4; i++)
                #pragma unroll
                for (int j = 0; j < 4; j++)
                    s[i][j] = fmaf(a[i], bb[j], s[i][j]);
        }

        if (kt == qt) {  // causal mask on diagonal tile
            #pragma unroll
            for (int i = 0; i < 4; i++)
                #pragma unroll
                for (int j = 0; j < 4; j++)
                    if (4 * tx + j > 4 * ty + i) s[i][j] = -INFINITY;
        }

        // Online softmax per row; row-owning threads are 16 contiguous lanes.
        #pragma unroll
        for (int i = 0; i < 4; i++) {
            float mx = fmaxf(fmaxf(s[i][0], s[i][1]), fmaxf(s[i][2], s[i][3]));
            #pragma unroll
            for (int w = 8; w >= 1; w >>= 1)
                mx = fmaxf(mx, __shfl_xor_sync(0xffffffffu, mx, w));
            const float mnew = fmaxf(m_i[i], mx);
            const float corr = __expf(m_i[i] - mnew);
            m_i[i] = mnew;
            float rs = 0.f;
            #pragma unroll
            for (int j = 0; j < 4; j++) {
                const float p = __expf(s[i][j] - mnew);
                sP[(4 * ty + i) * QT_STRIDE + 4 * tx + j] = p;
                rs += p;
            }
            #pragma unroll
            for (int w = 8; w >= 1; w >>= 1)
                rs += __shfl_xor_sync(0xffffffffu, rs, w);
            l_i[i] = l_i[i] * corr + rs;
            #pragma unroll
            for (int j = 0; j < 8; j++) O[i][j] *= corr;
        }
        __syncthreads();  // P visible

        // O += P * V  (rows 4ty+i, cols 8tx..8tx+7)
        #pragma unroll 2
        for (int k = 0; k < 64; k++) {
            float p[4];
            #pragma unroll
            for (int i = 0; i < 4; i++)
                p[i] = sP[(4 * ty + i) * QT_STRIDE + k];
            float4 v0 = *reinterpret_cast<const float4*>(&sV[k * V_STRIDE + 8 * tx]);
            float4 v1 = *reinterpret_cast<const float4*>(&sV[k * V_STRIDE + 8 * tx + 4]);
            const float v[8] = {v0.x, v0.y, v0.z, v0.w, v1.x, v1.y, v1.z, v1.w};
            #pragma unroll
            for (int i = 0; i < 4; i++)
                #pragma unroll
                for (int j = 0; j < 8; j++)
                    O[i][j] = fmaf(p[i], v[j], O[i][j]);
        }
        __syncthreads();  // before K/V/P overwrite
    }

    // Epilogue: normalize and store
    #pragma unroll
    for (int i = 0; i < 4; i++) {
        const float inv = 1.f / l_i[i];
        const int tok = b * SEQ + qt * 64 + 4 * ty + i;
        float* orow = out + (size_t)tok * HIDDEN + h * HEADD + 8 * tx;
        #pragma unroll
        for (int j = 0; j < 8; j++) orow[j] = O[i][j] * inv;
    }
}

// ---------------------------------------------------------------------------
// Launch
// ---------------------------------------------------------------------------
extern "C" void kernel_launch(void* const* d_in, const int* in_sizes, int n_in,
                              void* d_out, int out_size) {
    (void)in_sizes; (void)n_in; (void)out_size;
    const float* hidden  = (const float*)d_in[0];
    const float* w_qkv   = (const float*)d_in[1];
    const float* b_qkv   = (const float*)d_in[2];
    const float* w_dense = (const float*)d_in[3];
    const float* b_dense = (const float*)d_in[4];
    float* out = (float*)d_out;

    float* qkv;  cudaGetSymbolAddress((void**)&qkv,  g_qkv);
    float* attn; cudaGetSymbolAddress((void**)&attn, g_attn);

    static bool attr_set = false;
    if (!attr_set) {
        cudaFuncSetAttribute(flash_attn_kernel,
                             cudaFuncAttributeMaxDynamicSharedMemorySize, SM_BYTES);
        attr_set = true;
    }

    // 1) QKV projection: [8192,6144] = hidden[8192,2048] @ w_qkv[6144,2048]^T + b
    {
        dim3 grid(QKVN / 128, NTOK / 128);
        sgemm_bt_bias<<<grid, 256>>>(hidden, w_qkv, b_qkv, qkv, NTOK, QKVN, HIDDEN);
    }

    // 2) Causal flash attention
    {
        dim3 grid(SEQ / 64, NHEADS, BATCH);
        flash_attn_kernel<<<grid, 256, SM_BYTES>>>(qkv, attn);
    }

    // 3) Dense projection: [8192,2048] = attn @ w_dense[2048,2048]^T + b
    {
        dim3 grid(HIDDEN / 128, NTOK / 128);
        sgemm_bt_bias<<<grid, 256>>>(attn, w_dense, b_dense, out, NTOK, HIDDEN, HIDDEN);
    }
}

// round 3
// speedup vs baseline: 1.8458x; 1.8458x over previous
#include <cuda_runtime.h>
#include <math.h>
#include <stdint.h>

#define HIDDEN 2048
#define NHEADS 16
#define HEADD  128
#define BATCH  4
#define SEQ    2048
#define NTOK   (BATCH*SEQ)   /* 8192 */
#define QKVN   (3*HIDDEN)    /* 6144 */

// Scratch (device globals: the sanctioned no-alloc workaround)
__device__ float g_qkv[(size_t)NTOK * QKVN];    // ~201 MB
__device__ float g_attn[(size_t)NTOK * HIDDEN]; // ~67 MB

// ---------------------------------------------------------------------------
// TF32 tensor-core GEMM: C[M,N] = A[M,K] * B[N,K]^T + bias[N]
// CTA 128x128x16, 8 warps (4x2), warp tile 32x64, mma.m16n8k8.tf32.
// Smem rows padded to 20 floats (80B) -> conflict-free ldmatrix.
// Requires M%128==0, N%128==0, K%16==0.
// ---------------------------------------------------------------------------
__device__ __forceinline__ uint32_t f2tf32(float x) {
    uint32_t r;
    asm("cvt.rna.tf32.f32 %0, %1;" : "=r"(r) : "f"(x));
    return r;
}

#define LDM4(r, addr)                                                          \
    asm volatile("ldmatrix.sync.aligned.m8n8.x4.shared.b16 {%0,%1,%2,%3}, [%4];" \
                 : "=r"((r)[0]), "=r"((r)[1]), "=r"((r)[2]), "=r"((r)[3])      \
                 : "r"(addr))

#define MMA_TF32(cc, a, b0, b1)                                                \
    asm volatile("mma.sync.aligned.m16n8k8.row.col.f32.tf32.tf32.f32 "         \
                 "{%0,%1,%2,%3},{%4,%5,%6,%7},{%8,%9},{%0,%1,%2,%3};"          \
                 : "+f"((cc)[0]), "+f"((cc)[1]), "+f"((cc)[2]), "+f"((cc)[3])  \
                 : "r"((a)[0]), "r"((a)[1]), "r"((a)[2]), "r"((a)[3]),         \
                   "r"(b0), "r"(b1))

#define SM_STRIDE 20  /* floats per smem row (16 data + 4 pad), 80 bytes */

__global__ __launch_bounds__(256)
void gemm_tf32_bt_bias(const float* __restrict__ A, const float* __restrict__ B,
                       const float* __restrict__ bias, float* __restrict__ C,
                       int M, int N, int K) {
    __shared__ uint32_t As[2][128][SM_STRIDE];
    __shared__ uint32_t Bs[2][128][SM_STRIDE];

    const int tid  = threadIdx.x;
    const int warp = tid >> 5;
    const int lane = tid & 31;
    const int wm   = warp & 3;   // 0..3
    const int wn   = warp >> 2;  // 0..1
    const int row0 = blockIdx.y * 128;
    const int col0 = blockIdx.x * 128;

    // loader mapping: thread -> (row, 16B chunk)
    const int lr = tid >> 2;          // 0..63
    const int lc = (tid & 3) << 2;    // 0,4,8,12

    const float* aP0 = A + (size_t)(row0 + lr)      * K + lc;
    const float* aP1 = A + (size_t)(row0 + lr + 64) * K + lc;
    const float* bP0 = B + (size_t)(col0 + lr)      * K + lc;
    const float* bP1 = B + (size_t)(col0 + lr + 64) * K + lc;

    float c[2][8][4];
    #pragma unroll
    for (int mt = 0; mt < 2; mt++)
        #pragma unroll
        for (int nt = 0; nt < 8; nt++)
            #pragma unroll
            for (int q = 0; q < 4; q++) c[mt][nt][q] = 0.f;

    float4 pa0, pa1, pb0, pb1;

    // prologue: tile 0 -> regs -> smem buf 0
    pa0 = *(const float4*)(aP0);
    pa1 = *(const float4*)(aP1);
    pb0 = *(const float4*)(bP0);
    pb1 = *(const float4*)(bP1);
    {
        uint32_t* a0 = &As[0][lr][lc];
        a0[0]=f2tf32(pa0.x); a0[1]=f2tf32(pa0.y); a0[2]=f2tf32(pa0.z); a0[3]=f2tf32(pa0.w);
        uint32_t* a1 = &As[0][lr+64][lc];
        a1[0]=f2tf32(pa1.x); a1[1]=f2tf32(pa1.y); a1[2]=f2tf32(pa1.z); a1[3]=f2tf32(pa1.w);
        uint32_t* b0 = &Bs[0][lr][lc];
        b0[0]=f2tf32(pb0.x); b0[1]=f2tf32(pb0.y); b0[2]=f2tf32(pb0.z); b0[3]=f2tf32(pb0.w);
        uint32_t* b1 = &Bs[0][lr+64][lc];
        b1[0]=f2tf32(pb1.x); b1[1]=f2tf32(pb1.y); b1[2]=f2tf32(pb1.z); b1[3]=f2tf32(pb1.w);
    }
    __syncthreads();

    const int niter = K >> 4;
    int buf = 0;

    for (int it = 0; it < niter; it++) {
        const bool more = (it + 1 < niter);
        if (more) {
            const int off = (it + 1) << 4;
            pa0 = *(const float4*)(aP0 + off);
            pa1 = *(const float4*)(aP1 + off);
            pb0 = *(const float4*)(bP0 + off);
            pb1 = *(const float4*)(bP1 + off);
        }

        // compute on smem[buf]
        const uint32_t aBase = (uint32_t)__cvta_generic_to_shared(&As[buf][0][0]);
        const uint32_t bBase = (uint32_t)__cvta_generic_to_shared(&Bs[buf][0][0]);
        const uint32_t laneRow = (uint32_t)(lane & 15);
        const uint32_t hiOff   = (uint32_t)((lane >> 4) << 4);

        #pragma unroll
        for (int kk = 0; kk < 2; kk++) {
            uint32_t afr[2][4];
            #pragma unroll
            for (int mt = 0; mt < 2; mt++) {
                uint32_t addr = aBase + (wm * 32 + mt * 16 + laneRow) * (SM_STRIDE * 4)
                              + kk * 32 + hiOff;
                LDM4(afr[mt], addr);
            }
            #pragma unroll
            for (int p = 0; p < 4; p++) {
                uint32_t bfr[4];  // {b0_t0, b0_t1, b1_t0, b1_t1}
                uint32_t addr = bBase + (wn * 64 + p * 16 + laneRow) * (SM_STRIDE * 4)
                              + kk * 32 + hiOff;
                LDM4(bfr, addr);
                MMA_TF32(c[0][2*p],   afr[0], bfr[0], bfr[2]);
                MMA_TF32(c[0][2*p+1], afr[0], bfr[1], bfr[3]);
                MMA_TF32(c[1][2*p],   afr[1], bfr[0], bfr[2]);
                MMA_TF32(c[1][2*p+1], afr[1], bfr[1], bfr[3]);
            }
        }

        if (more) {
            const int nb = buf ^ 1;
            uint32_t* a0 = &As[nb][lr][lc];
            a0[0]=f2tf32(pa0.x); a0[1]=f2tf32(pa0.y); a0[2]=f2tf32(pa0.z); a0[3]=f2tf32(pa0.w);
            uint32_t* a1 = &As[nb][lr+64][lc];
            a1[0]=f2tf32(pa1.x); a1[1]=f2tf32(pa1.y); a1[2]=f2tf32(pa1.z); a1[3]=f2tf32(pa1.w);
            uint32_t* b0 = &Bs[nb][lr][lc];
            b0[0]=f2tf32(pb0.x); b0[1]=f2tf32(pb0.y); b0[2]=f2tf32(pb0.z); b0[3]=f2tf32(pb0.w);
            uint32_t* b1 = &Bs[nb][lr+64][lc];
            b1[0]=f2tf32(pb1.x); b1[1]=f2tf32(pb1.y); b1[2]=f2tf32(pb1.z); b1[3]=f2tf32(pb1.w);
            __syncthreads();
            buf = nb;
        }
    }

    // epilogue
    const int mrow0 = row0 + wm * 32;
    const int ncol0 = col0 + wn * 64;
    const int grp   = lane >> 2;
    const int tig   = lane & 3;
    #pragma unroll
    for (int mt = 0; mt < 2; mt++) {
        #pragma unroll
        for (int nt = 0; nt < 8; nt++) {
            const int row = mrow0 + mt * 16 + grp;
            const int col = ncol0 + nt * 8 + (tig << 1);
            const float bb0 = bias[col], bb1 = bias[col + 1];
            *(float2*)&C[(size_t)row * N + col] =
                make_float2(c[mt][nt][0] + bb0, c[mt][nt][1] + bb1);
            *(float2*)&C[(size_t)(row + 8) * N + col] =
                make_float2(c[mt][nt][2] + bb0, c[mt][nt][3] + bb1);
        }
    }
}

// ---------------------------------------------------------------------------
// Flash attention, fp32, causal. One block per (q-tile 64 rows, head, batch).
// ---------------------------------------------------------------------------
#define QT_STRIDE 68
#define V_STRIDE  132
#define SM_BYTES  ((128*QT_STRIDE + 128*QT_STRIDE + 64*V_STRIDE + 64*QT_STRIDE) * 4)

__global__ __launch_bounds__(256)
void flash_attn_kernel(const float* __restrict__ qkv, float* __restrict__ out) {
    extern __shared__ float sm[];
    float* sQt = sm;                         // [128][68]
    float* sKt = sQt + 128 * QT_STRIDE;      // [128][68]
    float* sV  = sKt + 128 * QT_STRIDE;      // [64][132]
    float* sP  = sV  + 64  * V_STRIDE;       // [64][68]

    const int tid = threadIdx.x;
    const int ty  = tid >> 4;
    const int tx  = tid & 15;
    const int qt  = blockIdx.x;
    const int h   = blockIdx.y;
    const int b   = blockIdx.z;

    const float scale = 0.08838834764831845f; // 1/sqrt(128)

    const float* qbase = qkv + ((size_t)(b * SEQ + qt * 64)) * QKVN + h * HEADD;
    for (int idx = tid; idx < 64 * 128; idx += 256) {
        const int r = idx >> 7, d = idx & 127;
        sQt[d * QT_STRIDE + r] = qbase[(size_t)r * QKVN + d] * scale;
    }

    float O[4][8];
    float m_i[4], l_i[4];
    #pragma unroll
    for (int i = 0; i < 4; i++) {
        m_i[i] = -INFINITY; l_i[i] = 0.f;
        #pragma unroll
        for (int j = 0; j < 8; j++) O[i][j] = 0.f;
    }

    for (int kt = 0; kt <= qt; kt++) {
        const float* kbase = qkv + ((size_t)(b * SEQ + kt * 64)) * QKVN + HIDDEN + h * HEADD;
        const float* vbase = kbase + HIDDEN;
        for (int idx = tid; idx < 64 * 128; idx += 256) {
            const int r = idx >> 7, d = idx & 127;
            sKt[d * QT_STRIDE + r] = kbase[(size_t)r * QKVN + d];
            sV[r * V_STRIDE + d]   = vbase[(size_t)r * QKVN + d];
        }
        __syncthreads();

        float s[4][4];
        #pragma unroll
        for (int i = 0; i < 4; i++)
            #pragma unroll
            for (int j = 0; j < 4; j++) s[i][j] = 0.f;

        #pragma unroll 2
        for (int d = 0; d < 128; d++) {
            float4 a4 = *reinterpret_cast<const float4*>(&sQt[d * QT_STRIDE + 4 * ty]);
            float4 b4 = *reinterpret_cast<const float4*>(&sKt[d * QT_STRIDE + 4 * tx]);
            const float a[4] = {a4.x, a4.y, a4.z, a4.w};
            const float bb[4] = {b4.x, b4.y, b4.z, b4.w};
            #pragma unroll
            for (int i = 0; i < 4; i++)
                #pragma unroll
                for (int j = 0; j < 4; j++)
                    s[i][j] = fmaf(a[i], bb[j], s[i][j]);
        }

        if (kt == qt) {
            #pragma unroll
            for (int i = 0; i < 4; i++)
                #pragma unroll
                for (int j = 0; j < 4; j++)
                    if (4 * tx + j > 4 * ty + i) s[i][j] = -INFINITY;
        }

        #pragma unroll
        for (int i = 0; i < 4; i++) {
            float mx = fmaxf(fmaxf(s[i][0], s[i][1]), fmaxf(s[i][2], s[i][3]));
            #pragma unroll
            for (int w = 8; w >= 1; w >>= 1)
                mx = fmaxf(mx, __shfl_xor_sync(0xffffffffu, mx, w));
            const float mnew = fmaxf(m_i[i], mx);
            const float corr = __expf(m_i[i] - mnew);
            m_i[i] = mnew;
            float rs = 0.f;
            #pragma unroll
            for (int j = 0; j < 4; j++) {
                const float p = __expf(s[i][j] - mnew);
                sP[(4 * ty + i) * QT_STRIDE + 4 * tx + j] = p;
                rs += p;
            }
            #pragma unroll
            for (int w = 8; w >= 1; w >>= 1)
                rs += __shfl_xor_sync(0xffffffffu, rs, w);
            l_i[i] = l_i[i] * corr + rs;
            #pragma unroll
            for (int j = 0; j < 8; j++) O[i][j] *= corr;
        }
        __syncthreads();

        #pragma unroll 2
        for (int k = 0; k < 64; k++) {
            float p[4];
            #pragma unroll
            for (int i = 0; i < 4; i++)
                p[i] = sP[(4 * ty + i) * QT_STRIDE + k];
            float4 v0 = *reinterpret_cast<const float4*>(&sV[k * V_STRIDE + 8 * tx]);
            float4 v1 = *reinterpret_cast<const float4*>(&sV[k * V_STRIDE + 8 * tx + 4]);
            const float v[8] = {v0.x, v0.y, v0.z, v0.w, v1.x, v1.y, v1.z, v1.w};
            #pragma unroll
            for (int i = 0; i < 4; i++)
                #pragma unroll
                for (int j = 0; j < 8; j++)
                    O[i][j] = fmaf(p[i], v[j], O[i][j]);
        }
        __syncthreads();
    }

    #pragma unroll
    for (int i = 0; i < 4; i++) {
        const float inv = 1.f / l_i[i];
        const int tok = b * SEQ + qt * 64 + 4 * ty + i;
        float* orow = out + (size_t)tok * HIDDEN + h * HEADD + 8 * tx;
        #pragma unroll
        for (int j = 0; j < 8; j++) orow[j] = O[i][j] * inv;
    }
}

// ---------------------------------------------------------------------------
// Launch
// ---------------------------------------------------------------------------
extern "C" void kernel_launch(void* const* d_in, const int* in_sizes, int n_in,
                              void* d_out, int out_size) {
    (void)in_sizes; (void)n_in; (void)out_size;
    const float* hidden  = (const float*)d_in[0];
    const float* w_qkv   = (const float*)d_in[1];
    const float* b_qkv   = (const float*)d_in[2];
    const float* w_dense = (const float*)d_in[3];
    const float* b_dense = (const float*)d_in[4];
    float* out = (float*)d_out;

    float* qkv;  cudaGetSymbolAddress((void**)&qkv,  g_qkv);
    float* attn; cudaGetSymbolAddress((void**)&attn, g_attn);

    static bool attr_set = false;
    if (!attr_set) {
        cudaFuncSetAttribute(flash_attn_kernel,
                             cudaFuncAttributeMaxDynamicSharedMemorySize, SM_BYTES);
        attr_set = true;
    }

    // 1) QKV projection: [8192,6144] = hidden @ w_qkv^T + b  (tf32 tensor cores)
    {
        dim3 grid(QKVN / 128, NTOK / 128);
        gemm_tf32_bt_bias<<<grid, 256>>>(hidden, w_qkv, b_qkv, qkv, NTOK, QKVN, HIDDEN);
    }

    // 2) Causal flash attention (fp32 SIMT)
    {
        dim3 grid(SEQ / 64, NHEADS, BATCH);
        flash_attn_kernel<<<grid, 256, SM_BYTES>>>(qkv, attn);
    }

    // 3) Dense projection: [8192,2048] = attn @ w_dense^T + b  (tf32 tensor cores)
    {
        dim3 grid(HIDDEN / 128, NTOK / 128);
        gemm_tf32_bt_bias<<<grid, 256>>>(attn, w_dense, b_dense, out, NTOK, HIDDEN, HIDDEN);
    }
}

// round 8
// speedup vs baseline: 3.3207x; 1.7990x over previous
#include <cuda_runtime.h>
#include <math.h>
#include <stdint.h>

#define HIDDEN 2048
#define NHEADS 16
#define HEADD  128
#define BATCH  4
#define SEQ    2048
#define NTOK   (BATCH*SEQ)   /* 8192 */
#define QKVN   (3*HIDDEN)    /* 6144 */

// Scratch (device globals: the sanctioned no-alloc workaround)
__device__ float g_qkv[(size_t)NTOK * QKVN];    // ~201 MB
__device__ float g_attn[(size_t)NTOK * HIDDEN]; // ~67 MB

__device__ __forceinline__ uint32_t f2tf32(float x) {
    uint32_t r;
    asm("cvt.rna.tf32.f32 %0, %1;" : "=r"(r) : "f"(x));
    return r;
}

#define LDM4(r, addr)                                                          \
    asm volatile("ldmatrix.sync.aligned.m8n8.x4.shared.b16 {%0,%1,%2,%3}, [%4];" \
                 : "=r"((r)[0]), "=r"((r)[1]), "=r"((r)[2]), "=r"((r)[3])      \
                 : "r"(addr))

#define MMA_TF32(cc, a, b0, b1)                                                \
    asm volatile("mma.sync.aligned.m16n8k8.row.col.f32.tf32.tf32.f32 "         \
                 "{%0,%1,%2,%3},{%4,%5,%6,%7},{%8,%9},{%0,%1,%2,%3};"          \
                 : "+f"((cc)[0]), "+f"((cc)[1]), "+f"((cc)[2]), "+f"((cc)[3])  \
                 : "r"((a)[0]), "r"((a)[1]), "r"((a)[2]), "r"((a)[3]),         \
                   "r"(b0), "r"(b1))

// ---------------------------------------------------------------------------
// TF32 tensor-core GEMM: C[M,N] = A[M,K] * B[N,K]^T + bias[N]
// ---------------------------------------------------------------------------
#define SM_STRIDE 20  /* floats per smem row (16 data + 4 pad), 80 bytes */

__global__ __launch_bounds__(256)
void gemm_tf32_bt_bias(const float* __restrict__ A, const float* __restrict__ B,
                       const float* __restrict__ bias, float* __restrict__ C,
                       int M, int N, int K) {
    __shared__ uint32_t As[2][128][SM_STRIDE];
    __shared__ uint32_t Bs[2][128][SM_STRIDE];

    const int tid  = threadIdx.x;
    const int warp = tid >> 5;
    const int lane = tid & 31;
    const int wm   = warp & 3;
    const int wn   = warp >> 2;
    const int row0 = blockIdx.y * 128;
    const int col0 = blockIdx.x * 128;

    const int lr = tid >> 2;
    const int lc = (tid & 3) << 2;

    const float* aP0 = A + (size_t)(row0 + lr)      * K + lc;
    const float* aP1 = A + (size_t)(row0 + lr + 64) * K + lc;
    const float* bP0 = B + (size_t)(col0 + lr)      * K + lc;
    const float* bP1 = B + (size_t)(col0 + lr + 64) * K + lc;

    float c[2][8][4];
    #pragma unroll
    for (int mt = 0; mt < 2; mt++)
        #pragma unroll
        for (int nt = 0; nt < 8; nt++)
            #pragma unroll
            for (int q = 0; q < 4; q++) c[mt][nt][q] = 0.f;

    float4 pa0, pa1, pb0, pb1;
    pa0 = *(const float4*)(aP0);
    pa1 = *(const float4*)(aP1);
    pb0 = *(const float4*)(bP0);
    pb1 = *(const float4*)(bP1);
    {
        uint32_t* a0 = &As[0][lr][lc];
        a0[0]=f2tf32(pa0.x); a0[1]=f2tf32(pa0.y); a0[2]=f2tf32(pa0.z); a0[3]=f2tf32(pa0.w);
        uint32_t* a1 = &As[0][lr+64][lc];
        a1[0]=f2tf32(pa1.x); a1[1]=f2tf32(pa1.y); a1[2]=f2tf32(pa1.z); a1[3]=f2tf32(pa1.w);
        uint32_t* b0 = &Bs[0][lr][lc];
        b0[0]=f2tf32(pb0.x); b0[1]=f2tf32(pb0.y); b0[2]=f2tf32(pb0.z); b0[3]=f2tf32(pb0.w);
        uint32_t* b1 = &Bs[0][lr+64][lc];
        b1[0]=f2tf32(pb1.x); b1[1]=f2tf32(pb1.y); b1[2]=f2tf32(pb1.z); b1[3]=f2tf32(pb1.w);
    }
    __syncthreads();

    const int niter = K >> 4;
    int buf = 0;

    for (int it = 0; it < niter; it++) {
        const bool more = (it + 1 < niter);
        if (more) {
            const int off = (it + 1) << 4;
            pa0 = *(const float4*)(aP0 + off);
            pa1 = *(const float4*)(aP1 + off);
            pb0 = *(const float4*)(bP0 + off);
            pb1 = *(const float4*)(bP1 + off);
        }

        const uint32_t aBase = (uint32_t)__cvta_generic_to_shared(&As[buf][0][0]);
        const uint32_t bBase = (uint32_t)__cvta_generic_to_shared(&Bs[buf][0][0]);
        const uint32_t laneRow = (uint32_t)(lane & 15);
        const uint32_t hiOff   = (uint32_t)((lane >> 4) << 4);

        #pragma unroll
        for (int kk = 0; kk < 2; kk++) {
            uint32_t afr[2][4];
            #pragma unroll
            for (int mt = 0; mt < 2; mt++) {
                uint32_t addr = aBase + (wm * 32 + mt * 16 + laneRow) * (SM_STRIDE * 4)
                              + kk * 32 + hiOff;
                LDM4(afr[mt], addr);
            }
            #pragma unroll
            for (int p = 0; p < 4; p++) {
                uint32_t bfr[4];
                uint32_t addr = bBase + (wn * 64 + p * 16 + laneRow) * (SM_STRIDE * 4)
                              + kk * 32 + hiOff;
                LDM4(bfr, addr);
                MMA_TF32(c[0][2*p],   afr[0], bfr[0], bfr[2]);
                MMA_TF32(c[0][2*p+1], afr[0], bfr[1], bfr[3]);
                MMA_TF32(c[1][2*p],   afr[1], bfr[0], bfr[2]);
                MMA_TF32(c[1][2*p+1], afr[1], bfr[1], bfr[3]);
            }
        }

        if (more) {
            const int nb = buf ^ 1;
            uint32_t* a0 = &As[nb][lr][lc];
            a0[0]=f2tf32(pa0.x); a0[1]=f2tf32(pa0.y); a0[2]=f2tf32(pa0.z); a0[3]=f2tf32(pa0.w);
            uint32_t* a1 = &As[nb][lr+64][lc];
            a1[0]=f2tf32(pa1.x); a1[1]=f2tf32(pa1.y); a1[2]=f2tf32(pa1.z); a1[3]=f2tf32(pa1.w);
            uint32_t* b0 = &Bs[nb][lr][lc];
            b0[0]=f2tf32(pb0.x); b0[1]=f2tf32(pb0.y); b0[2]=f2tf32(pb0.z); b0[3]=f2tf32(pb0.w);
            uint32_t* b1 = &Bs[nb][lr+64][lc];
            b1[0]=f2tf32(pb1.x); b1[1]=f2tf32(pb1.y); b1[2]=f2tf32(pb1.z); b1[3]=f2tf32(pb1.w);
            __syncthreads();
            buf = nb;
        }
    }

    const int mrow0 = row0 + wm * 32;
    const int ncol0 = col0 + wn * 64;
    const int grp   = lane >> 2;
    const int tig   = lane & 3;
    #pragma unroll
    for (int mt = 0; mt < 2; mt++) {
        #pragma unroll
        for (int nt = 0; nt < 8; nt++) {
            const int row = mrow0 + mt * 16 + grp;
            const int col = ncol0 + nt * 8 + (tig << 1);
            const float bb0 = bias[col], bb1 = bias[col + 1];
            *(float2*)&C[(size_t)row * N + col] =
                make_float2(c[mt][nt][0] + bb0, c[mt][nt][1] + bb1);
            *(float2*)&C[(size_t)(row + 8) * N + col] =
                make_float2(c[mt][nt][2] + bb0, c[mt][nt][3] + bb1);
        }
    }
}

// ---------------------------------------------------------------------------
// Tensor-core flash attention (tf32 mma), causal.
// Bq=128, Bk=64. 256 threads = 8 warps; warp w owns q-rows w*16..w*16+15.
// Smem: sQ[128][132] tf32(scaled), sK[64][132], sVt[128][68], sP[128][68].
// ---------------------------------------------------------------------------
#define AQ_STRIDE 132
#define AP_STRIDE 68
#define ASM_FLOATS (128*AQ_STRIDE + 64*AQ_STRIDE + 128*AP_STRIDE + 128*AP_STRIDE)
#define ASM_BYTES  (ASM_FLOATS * 4)

__global__ __launch_bounds__(256)
void flash_attn_tc(const float* __restrict__ qkv, float* __restrict__ out) {
    extern __shared__ float sm[];
    float* sQ  = sm;                          // [128][132]
    float* sK  = sQ  + 128 * AQ_STRIDE;       // [64][132]
    float* sVt = sK  + 64  * AQ_STRIDE;       // [128][68]
    float* sP  = sVt + 128 * AP_STRIDE;       // [128][68]

    const int tid  = threadIdx.x;
    const int warp = tid >> 5;
    const int lane = tid & 31;
    const int qt   = gridDim.x - 1 - blockIdx.x;  // heavy tiles first
    const int h    = blockIdx.y;
    const int b    = blockIdx.z;

    const float scale = 0.08838834764831845f; // 1/sqrt(128)

    // Load Q tile (scaled -> tf32), natural layout
    const float* qbase = qkv + (size_t)(b * SEQ + qt * 128) * QKVN + h * HEADD;
    for (int idx = tid; idx < 128 * 32; idx += 256) {
        const int r = idx >> 5, c = (idx & 31) << 2;
        float4 v = *(const float4*)(qbase + (size_t)r * QKVN + c);
        uint32_t* d = (uint32_t*)&sQ[r * AQ_STRIDE + c];
        d[0] = f2tf32(v.x * scale); d[1] = f2tf32(v.y * scale);
        d[2] = f2tf32(v.z * scale); d[3] = f2tf32(v.w * scale);
    }

    float o[16][4];
    #pragma unroll
    for (int nt = 0; nt < 16; nt++)
        #pragma unroll
        for (int q = 0; q < 4; q++) o[nt][q] = 0.f;
    float m0 = -INFINITY, m1 = -INFINITY, l0 = 0.f, l1 = 0.f;

    const int grp = lane >> 2;
    const int tig = lane & 3;
    const uint32_t laneRow = (uint32_t)(lane & 15);
    const uint32_t hiOff   = (uint32_t)((lane >> 4) << 4);
    const uint32_t sQb  = (uint32_t)__cvta_generic_to_shared(sQ);
    const uint32_t sKb  = (uint32_t)__cvta_generic_to_shared(sK);
    const uint32_t sVtb = (uint32_t)__cvta_generic_to_shared(sVt);
    const uint32_t sPb  = (uint32_t)__cvta_generic_to_shared(sP);

    const int qr0 = qt * 128 + warp * 16 + grp;  // global q-row of low half

    const int ntiles = 2 * qt + 2;
    for (int j = 0; j < ntiles; j++) {
        // Load K (natural) and V (transposed) for this tile
        const float* kbase = qkv + (size_t)(b * SEQ + j * 64) * QKVN + HIDDEN + h * HEADD;
        const float* vbase = kbase + HIDDEN;
        for (int idx = tid; idx < 64 * 32; idx += 256) {
            const int r = idx >> 5, c = (idx & 31) << 2;
            float4 v = *(const float4*)(kbase + (size_t)r * QKVN + c);
            uint32_t* d = (uint32_t*)&sK[r * AQ_STRIDE + c];
            d[0] = f2tf32(v.x); d[1] = f2tf32(v.y);
            d[2] = f2tf32(v.z); d[3] = f2tf32(v.w);
        }
        for (int idx = tid; idx < 16 * 128; idx += 256) {
            const int t4 = idx >> 7, dd = idx & 127;  // tok block of 4, feature
            uint32_t r0 = f2tf32(vbase[(size_t)(t4 * 4 + 0) * QKVN + dd]);
            uint32_t r1 = f2tf32(vbase[(size_t)(t4 * 4 + 1) * QKVN + dd]);
            uint32_t r2 = f2tf32(vbase[(size_t)(t4 * 4 + 2) * QKVN + dd]);
            uint32_t r3 = f2tf32(vbase[(size_t)(t4 * 4 + 3) * QKVN + dd]);
            uint32_t* d = (uint32_t*)&sVt[dd * AP_STRIDE + t4 * 4];
            d[0] = r0; d[1] = r1; d[2] = r2; d[3] = r3;
        }
        __syncthreads();

        const bool active = (j * 64 <= qt * 128 + warp * 16 + 15);
        if (active) {
            // S = Q K^T (scaled): warp tile 16x64
            float s[8][4];
            #pragma unroll
            for (int nt = 0; nt < 8; nt++)
                #pragma unroll
                for (int q = 0; q < 4; q++) s[nt][q] = 0.f;

            #pragma unroll
            for (int ks = 0; ks < 16; ks++) {
                uint32_t afr[4];
                LDM4(afr, sQb + (warp * 16 + laneRow) * (AQ_STRIDE * 4) + ks * 32 + hiOff);
                #pragma unroll
                for (int p = 0; p < 4; p++) {
                    uint32_t bfr[4];
                    LDM4(bfr, sKb + (p * 16 + laneRow) * (AQ_STRIDE * 4) + ks * 32 + hiOff);
                    MMA_TF32(s[2*p],   afr, bfr[0], bfr[2]);
                    MMA_TF32(s[2*p+1], afr, bfr[1], bfr[3]);
                }
            }

            // causal mask (only tiles overlapping the diagonal)
            if (j >= 2 * qt) {
                #pragma unroll
                for (int nt = 0; nt < 8; nt++) {
                    const int gk0 = j * 64 + nt * 8 + (tig << 1);
                    #pragma unroll
                    for (int q = 0; q < 4; q++) {
                        const int gk = gk0 + (q & 1);
                        const int gq = qr0 + ((q >= 2) ? 8 : 0);
                        if (gk > gq) s[nt][q] = -INFINITY;
                    }
                }
            }

            // online softmax (rows grp and grp+8; 4 lanes per row group)
            float mx0 = -INFINITY, mx1 = -INFINITY;
            #pragma unroll
            for (int nt = 0; nt < 8; nt++) {
                mx0 = fmaxf(mx0, fmaxf(s[nt][0], s[nt][1]));
                mx1 = fmaxf(mx1, fmaxf(s[nt][2], s[nt][3]));
            }
            #pragma unroll
            for (int w = 1; w <= 2; w <<= 1) {
                mx0 = fmaxf(mx0, __shfl_xor_sync(0xffffffffu, mx0, w));
                mx1 = fmaxf(mx1, __shfl_xor_sync(0xffffffffu, mx1, w));
            }
            const float mn0 = fmaxf(m0, mx0), mn1 = fmaxf(m1, mx1);
            const float c0 = __expf(m0 - mn0), c1 = __expf(m1 - mn1);
            m0 = mn0; m1 = mn1;

            float rs0 = 0.f, rs1 = 0.f;
            const int pr0 = (warp * 16 + grp) * AP_STRIDE + (tig << 1);
            #pragma unroll
            for (int nt = 0; nt < 8; nt++) {
                s[nt][0] = __expf(s[nt][0] - mn0);
                s[nt][1] = __expf(s[nt][1] - mn0);
                s[nt][2] = __expf(s[nt][2] - mn1);
                s[nt][3] = __expf(s[nt][3] - mn1);
                rs0 += s[nt][0] + s[nt][1];
                rs1 += s[nt][2] + s[nt][3];
                uint32_t* p0 = (uint32_t*)&sP[pr0 + nt * 8];
                p0[0] = f2tf32(s[nt][0]); p0[1] = f2tf32(s[nt][1]);
                uint32_t* p1 = (uint32_t*)&sP[pr0 + 8 * AP_STRIDE + nt * 8];
                p1[0] = f2tf32(s[nt][2]); p1[1] = f2tf32(s[nt][3]);
            }
            #pragma unroll
            for (int w = 1; w <= 2; w <<= 1) {
                rs0 += __shfl_xor_sync(0xffffffffu, rs0, w);
                rs1 += __shfl_xor_sync(0xffffffffu, rs1, w);
            }
            l0 = l0 * c0 + rs0;
            l1 = l1 * c1 + rs1;

            #pragma unroll
            for (int nt = 0; nt < 16; nt++) {
                o[nt][0] *= c0; o[nt][1] *= c0;
                o[nt][2] *= c1; o[nt][3] *= c1;
            }
            __syncwarp();

            // O += P V : warp tile 16x128, k=64
            #pragma unroll
            for (int ks = 0; ks < 8; ks++) {
                uint32_t afr[4];
                LDM4(afr, sPb + (warp * 16 + laneRow) * (AP_STRIDE * 4) + ks * 32 + hiOff);
                #pragma unroll
                for (int p = 0; p < 8; p++) {
                    uint32_t bfr[4];
                    LDM4(bfr, sVtb + (p * 16 + laneRow) * (AP_STRIDE * 4) + ks * 32 + hiOff);
                    MMA_TF32(o[2*p],   afr, bfr[0], bfr[2]);
                    MMA_TF32(o[2*p+1], afr, bfr[1], bfr[3]);
                }
            }
        }
        __syncthreads();
    }

    // epilogue: normalize, store
    const float inv0 = 1.f / l0, inv1 = 1.f / l1;
    const int tok0 = b * SEQ + qt * 128 + warp * 16 + grp;
    #pragma unroll
    for (int nt = 0; nt < 16; nt++) {
        const int col = h * HEADD + nt * 8 + (tig << 1);
        *(float2*)&out[(size_t)tok0 * HIDDEN + col] =
            make_float2(o[nt][0] * inv0, o[nt][1] * inv0);
        *(float2*)&out[(size_t)(tok0 + 8) * HIDDEN + col] =
            make_float2(o[nt][2] * inv1, o[nt][3] * inv1);
    }
}

// ---------------------------------------------------------------------------
// Launch
// ---------------------------------------------------------------------------
extern "C" void kernel_launch(void* const* d_in, const int* in_sizes, int n_in,
                              void* d_out, int out_size) {
    (void)in_sizes; (void)n_in; (void)out_size;
    const float* hidden  = (const float*)d_in[0];
    const float* w_qkv   = (const float*)d_in[1];
    const float* b_qkv   = (const float*)d_in[2];
    const float* w_dense = (const float*)d_in[3];
    const float* b_dense = (const float*)d_in[4];
    float* out = (float*)d_out;

    float* qkv;  cudaGetSymbolAddress((void**)&qkv,  g_qkv);
    float* attn; cudaGetSymbolAddress((void**)&attn, g_attn);

    static bool attr_set = false;
    if (!attr_set) {
        cudaFuncSetAttribute(flash_attn_tc,
                             cudaFuncAttributeMaxDynamicSharedMemorySize, ASM_BYTES);
        attr_set = true;
    }

    // 1) QKV projection (tf32 tensor cores)
    {
        dim3 grid(QKVN / 128, NTOK / 128);
        gemm_tf32_bt_bias<<<grid, 256>>>(hidden, w_qkv, b_qkv, qkv, NTOK, QKVN, HIDDEN);
    }

    // 2) Causal flash attention (tf32 tensor cores)
    {
        dim3 grid(SEQ / 128, NHEADS, BATCH);
        flash_attn_tc<<<grid, 256, ASM_BYTES>>>(qkv, attn);
    }

    // 3) Dense projection (tf32 tensor cores)
    {
        dim3 grid(HIDDEN / 128, NTOK / 128);
        gemm_tf32_bt_bias<<<grid, 256>>>(attn, w_dense, b_dense, out, NTOK, HIDDEN, HIDDEN);
    }
}